// round 1
// baseline (speedup 1.0000x reference)
#include <cuda_runtime.h>
#include <math.h>

#define BB 4
#define SS 1024
#define DD 1024
#define HH 16
#define DKK 64
#define BH (BB*HH)

// ---- scratch (device globals; no allocation allowed) ----
__device__ float g_q[BH*SS*DKK];        // 16 MB  [b,h,s,dk]
__device__ float g_k[BH*SS*DKK];        // 16 MB
__device__ float g_v[BH*SS*DKK];        // 16 MB
__device__ float g_scores[67108864];    // 256 MB [b,h,q,k]
__device__ float g_ctx[BB*SS*DD];       // 16 MB  [b,s,h*dk]
__device__ float g_bias[(2*SS-1)*HH];   // bias by delta = k - q

// ------------------------------------------------------------------
// Bias table: g_bias[(rp+S-1)*H + h] = rel_bias[bucket(rp)*H + h]
// ------------------------------------------------------------------
__global__ void bias_kernel(const float* __restrict__ rel_bias) {
    int idx = blockIdx.x * blockDim.x + threadIdx.x;
    const int total = (2*SS-1)*HH;
    if (idx >= total) return;
    int d = idx / HH;
    int h = idx - d*HH;
    int rp = d - (SS - 1);
    int rb = (rp > 0) ? 16 : 0;
    int n = rp < 0 ? -rp : rp;
    int b;
    if (n < 8) {
        b = n;
    } else {
        double v = log((double)n / 8.0) / log(16.0) * 8.0;
        int large = 8 + (int)v;
        b = large < 15 ? large : 15;
    }
    int bucket = rb + b;
    g_bias[idx] = rel_bias[bucket*HH + h];
}

// ------------------------------------------------------------------
// SGEMM: C[m,n] = sum_k A[m,k] * W[n,k]
//   A: [4096,1024] row-major, W: [1024,1024] row-major (N,K)
//   mode 0: C row-major [4096,1024]
//   mode 1: head-split  C[((b*H+h)*S+s)*DK+dk], m=b*S+s, n=h*DK+dk
// 128x128 tile, BK=8, 256 threads, 8x8 per thread.
// ------------------------------------------------------------------
__global__ __launch_bounds__(256) void sgemm_kernel(
    const float* __restrict__ A, const float* __restrict__ W,
    float* __restrict__ C, int mode)
{
    __shared__ __align__(16) float As[8][128];
    __shared__ __align__(16) float Bs[8][128];

    const int tid = threadIdx.x;
    const int bx = blockIdx.x;   // n tile (0..7)
    const int by = blockIdx.y;   // m tile (0..31)

    const int tx = tid & 15;
    const int ty = tid >> 4;
    const int m0 = ty * 8;
    const int n0 = tx * 8;

    const int l_row = tid >> 1;          // 0..127
    const int l_k   = (tid & 1) * 4;     // 0 or 4

    const float* Aptr = A + (size_t)(by*128 + l_row)*1024;
    const float* Wptr = W + (size_t)(bx*128 + l_row)*1024;

    float acc[8][8];
    #pragma unroll
    for (int i = 0; i < 8; i++)
        #pragma unroll
        for (int j = 0; j < 8; j++) acc[i][j] = 0.f;

    for (int kt = 0; kt < 1024; kt += 8) {
        float4 av = *(const float4*)(Aptr + kt + l_k);
        float4 bv = *(const float4*)(Wptr + kt + l_k);
        __syncthreads();
        As[l_k+0][l_row] = av.x; As[l_k+1][l_row] = av.y;
        As[l_k+2][l_row] = av.z; As[l_k+3][l_row] = av.w;
        Bs[l_k+0][l_row] = bv.x; Bs[l_k+1][l_row] = bv.y;
        Bs[l_k+2][l_row] = bv.z; Bs[l_k+3][l_row] = bv.w;
        __syncthreads();
        #pragma unroll
        for (int kk = 0; kk < 8; ++kk) {
            float ar[8], br[8];
            *(float4*)&ar[0] = *(const float4*)&As[kk][m0];
            *(float4*)&ar[4] = *(const float4*)&As[kk][m0+4];
            *(float4*)&br[0] = *(const float4*)&Bs[kk][n0];
            *(float4*)&br[4] = *(const float4*)&Bs[kk][n0+4];
            #pragma unroll
            for (int i = 0; i < 8; i++)
                #pragma unroll
                for (int j = 0; j < 8; j++)
                    acc[i][j] = fmaf(ar[i], br[j], acc[i][j]);
        }
    }

    if (mode == 0) {
        #pragma unroll
        for (int i = 0; i < 8; i++) {
            int m = by*128 + m0 + i;
            float* crow = C + (size_t)m*1024 + bx*128 + n0;
            float4 v0 = make_float4(acc[i][0], acc[i][1], acc[i][2], acc[i][3]);
            float4 v1 = make_float4(acc[i][4], acc[i][5], acc[i][6], acc[i][7]);
            *(float4*)(crow)     = v0;
            *(float4*)(crow + 4) = v1;
        }
    } else {
        int n_base = bx*128 + n0;
        int h = n_base >> 6;
        int dk0 = n_base & 63;
        #pragma unroll
        for (int i = 0; i < 8; i++) {
            int m = by*128 + m0 + i;
            int b = m >> 10, s = m & 1023;
            float* dst = C + (size_t)(((b*HH + h)*SS + s))*DKK + dk0;
            float4 v0 = make_float4(acc[i][0], acc[i][1], acc[i][2], acc[i][3]);
            float4 v1 = make_float4(acc[i][4], acc[i][5], acc[i][6], acc[i][7]);
            *(float4*)(dst)     = v0;
            *(float4*)(dst + 4) = v1;
        }
    }
}

// ------------------------------------------------------------------
// Scores: per (b,h): S[m,n] = Q[m,:] . K[n,:] + bias(n-m, h)
// 64x64 output tile per block, K=64 fully resident. 4x4 per thread.
// ------------------------------------------------------------------
__global__ __launch_bounds__(256) void scores_kernel() {
    __shared__ __align__(16) float Qs[64][68];
    __shared__ __align__(16) float Ks[64][68];

    const int tid = threadIdx.x;
    const int bh = blockIdx.z;
    const int h  = bh & (HH-1);
    const int mbase = blockIdx.y * 64;
    const int nbase = blockIdx.x * 64;

    const float* Q = g_q + (size_t)bh*SS*DKK + (size_t)mbase*DKK;
    const float* K = g_k + (size_t)bh*SS*DKK + (size_t)nbase*DKK;

    // load tiles transposed: Qs[k][m], Ks[k][n]
    for (int i = tid; i < 64*16; i += 256) {
        int r  = i >> 4;
        int kc = (i & 15) << 2;
        float4 q = *(const float4*)(Q + r*DKK + kc);
        Qs[kc+0][r] = q.x; Qs[kc+1][r] = q.y; Qs[kc+2][r] = q.z; Qs[kc+3][r] = q.w;
        float4 k = *(const float4*)(K + r*DKK + kc);
        Ks[kc+0][r] = k.x; Ks[kc+1][r] = k.y; Ks[kc+2][r] = k.z; Ks[kc+3][r] = k.w;
    }
    __syncthreads();

    const int tx = tid & 15, ty = tid >> 4;
    const int m0 = ty*4, n0 = tx*4;

    float acc[4][4];
    #pragma unroll
    for (int i = 0; i < 4; i++)
        #pragma unroll
        for (int j = 0; j < 4; j++) acc[i][j] = 0.f;

    #pragma unroll 8
    for (int k = 0; k < 64; k++) {
        float4 q4 = *(const float4*)&Qs[k][m0];
        float4 k4 = *(const float4*)&Ks[k][n0];
        float qa[4] = {q4.x, q4.y, q4.z, q4.w};
        float ka[4] = {k4.x, k4.y, k4.z, k4.w};
        #pragma unroll
        for (int i = 0; i < 4; i++)
            #pragma unroll
            for (int j = 0; j < 4; j++)
                acc[i][j] = fmaf(qa[i], ka[j], acc[i][j]);
    }

    #pragma unroll
    for (int i = 0; i < 4; i++) {
        int mg = mbase + m0 + i;
        int ng = nbase + n0;
        const float* bt = g_bias + (size_t)(ng - mg + (SS-1))*HH + h;
        float4 o;
        o.x = acc[i][0] + bt[0*HH];
        o.y = acc[i][1] + bt[1*HH];
        o.z = acc[i][2] + bt[2*HH];
        o.w = acc[i][3] + bt[3*HH];
        *(float4*)&g_scores[((size_t)bh*SS + mg)*SS + ng] = o;
    }
}

// ------------------------------------------------------------------
// Softmax over last dim (1024), one block (256 threads) per row.
// ------------------------------------------------------------------
__global__ __launch_bounds__(256) void softmax_kernel() {
    __shared__ float redm[8];
    __shared__ float reds[8];
    size_t row = blockIdx.x;
    float* p = g_scores + row * SS;
    int t = threadIdx.x;
    int lane = t & 31, wid = t >> 5;

    float4 v = ((const float4*)p)[t];
    float m = fmaxf(fmaxf(v.x, v.y), fmaxf(v.z, v.w));
    #pragma unroll
    for (int o = 16; o; o >>= 1) m = fmaxf(m, __shfl_xor_sync(0xffffffffu, m, o));
    if (lane == 0) redm[wid] = m;
    __syncthreads();
    m = redm[0];
    #pragma unroll
    for (int i = 1; i < 8; i++) m = fmaxf(m, redm[i]);

    v.x = expf(v.x - m); v.y = expf(v.y - m);
    v.z = expf(v.z - m); v.w = expf(v.w - m);
    float s = v.x + v.y + v.z + v.w;
    #pragma unroll
    for (int o = 16; o; o >>= 1) s += __shfl_xor_sync(0xffffffffu, s, o);
    if (lane == 0) reds[wid] = s;
    __syncthreads();
    s = reds[0];
    #pragma unroll
    for (int i = 1; i < 8; i++) s += reds[i];

    float inv = 1.0f / s;
    v.x *= inv; v.y *= inv; v.z *= inv; v.w *= inv;
    ((float4*)p)[t] = v;
}

// ------------------------------------------------------------------
// ctx: per (b,h): C[m,d] = sum_k P[m,k] * V[k,d]   (m tile=64, d=64 full)
// writes g_ctx[b, s, h*64 + d]
// ------------------------------------------------------------------
__global__ __launch_bounds__(256) void ctx_kernel() {
    __shared__ __align__(16) float Ps[64][68];   // [k][m]
    __shared__ __align__(16) float Vs[64][68];   // [k][d]

    const int tid = threadIdx.x;
    const int bh = blockIdx.y;
    const int mbase = blockIdx.x * 64;
    const int b = bh >> 4, h = bh & 15;

    const int tx = tid & 15, ty = tid >> 4;
    const int m0 = ty*4, n0 = tx*4;

    float acc[4][4];
    #pragma unroll
    for (int i = 0; i < 4; i++)
        #pragma unroll
        for (int j = 0; j < 4; j++) acc[i][j] = 0.f;

    for (int kt = 0; kt < SS; kt += 64) {
        __syncthreads();
        for (int i = tid; i < 64*16; i += 256) {
            int r  = i >> 4;
            int kc = (i & 15) << 2;
            float4 pv = *(const float4*)(g_scores + ((size_t)bh*SS + mbase + r)*SS + kt + kc);
            Ps[kc+0][r] = pv.x; Ps[kc+1][r] = pv.y; Ps[kc+2][r] = pv.z; Ps[kc+3][r] = pv.w;
            float4 vv = *(const float4*)(g_v + ((size_t)bh*SS + kt + r)*DKK + kc);
            *(float4*)&Vs[r][kc] = vv;
        }
        __syncthreads();
        #pragma unroll 8
        for (int k = 0; k < 64; k++) {
            float4 p4 = *(const float4*)&Ps[k][m0];
            float4 v4 = *(const float4*)&Vs[k][n0];
            float pa[4] = {p4.x, p4.y, p4.z, p4.w};
            float va[4] = {v4.x, v4.y, v4.z, v4.w};
            #pragma unroll
            for (int i = 0; i < 4; i++)
                #pragma unroll
                for (int j = 0; j < 4; j++)
                    acc[i][j] = fmaf(pa[i], va[j], acc[i][j]);
        }
    }

    #pragma unroll
    for (int i = 0; i < 4; i++) {
        int s = mbase + m0 + i;
        float* dst = g_ctx + ((size_t)(b*SS + s))*DD + h*DKK + n0;
        *(float4*)dst = make_float4(acc[i][0], acc[i][1], acc[i][2], acc[i][3]);
    }
}

// ------------------------------------------------------------------
extern "C" void kernel_launch(void* const* d_in, const int* in_sizes, int n_in,
                              void* d_out, int out_size) {
    const float* hidden   = (const float*)d_in[0];
    const float* Wq       = (const float*)d_in[1];
    const float* Wk       = (const float*)d_in[2];
    const float* Wv       = (const float*)d_in[3];
    const float* Wo       = (const float*)d_in[4];
    const float* rel_bias = (const float*)d_in[5];
    float* out = (float*)d_out;

    float *pq, *pk, *pv, *pctx;
    cudaGetSymbolAddress((void**)&pq,   g_q);
    cudaGetSymbolAddress((void**)&pk,   g_k);
    cudaGetSymbolAddress((void**)&pv,   g_v);
    cudaGetSymbolAddress((void**)&pctx, g_ctx);

    // 1. bias table
    {
        int total = (2*SS-1)*HH;
        bias_kernel<<<(total + 255)/256, 256>>>(rel_bias);
    }
    // 2. QKV projections (head-split output)
    dim3 ggrid(8, 32);
    sgemm_kernel<<<ggrid, 256>>>(hidden, Wq, pq, 1);
    sgemm_kernel<<<ggrid, 256>>>(hidden, Wk, pk, 1);
    sgemm_kernel<<<ggrid, 256>>>(hidden, Wv, pv, 1);
    // 3. scores + bias
    scores_kernel<<<dim3(16, 16, BH), 256>>>();
    // 4. softmax
    softmax_kernel<<<BH*SS, 256>>>();
    // 5. ctx = P @ V  (writes [B,S,H*DK])
    ctx_kernel<<<dim3(16, BH), 256>>>();
    // 6. output projection
    sgemm_kernel<<<ggrid, 256>>>(pctx, Wo, out, 0);
}

// round 3
// speedup vs baseline: 1.4820x; 1.4820x over previous
#include <cuda_runtime.h>
#include <cuda_bf16.h>
#include <math.h>
#include <stdint.h>

#define BB 4
#define SS 1024
#define DD 1024
#define HH 16
#define DKK 64
#define BH (BB*HH)

// ---- scratch (device globals; no allocation allowed) ----
__device__ float g_q[BH*SS*DKK];        // 16 MB  [b,h,s,dk]
__device__ float g_k[BH*SS*DKK];        // 16 MB
__device__ float g_v[BH*SS*DKK];        // 16 MB
__device__ float g_scores[67108864];    // 256 MB [b,h,q,k]
__device__ float g_ctx[BB*SS*DD];       // 16 MB  [b,s,h*dk]
__device__ float g_bias[(2*SS-1)*HH];   // bias by delta = k - q

// bf16x3 split buffers (16B aligned for cp.async)
__device__ __align__(16) __nv_bfloat16 g_ahi[4096*1024];
__device__ __align__(16) __nv_bfloat16 g_alo[4096*1024];
__device__ __align__(16) __nv_bfloat16 g_whi[1024*1024];
__device__ __align__(16) __nv_bfloat16 g_wlo[1024*1024];

// ================= PTX helpers (baseline ISA only) =================
__device__ __forceinline__ uint32_t smem_u32(const void* p) {
    uint32_t a;
    asm("{ .reg .u64 t; cvta.to.shared.u64 t, %1; cvt.u32.u64 %0, t; }"
        : "=r"(a) : "l"(p));
    return a;
}

#define CP_ASYNC16(sa, ga) \
    asm volatile("cp.async.cg.shared.global [%0], [%1], 16;" \
        :: "r"(sa), "l"(ga) : "memory")
#define CP_COMMIT() asm volatile("cp.async.commit_group;" ::: "memory")
#define CP_WAIT1()  asm volatile("cp.async.wait_group 1;" ::: "memory")

__device__ __forceinline__ void ldsm4(uint32_t addr, uint32_t& r0, uint32_t& r1,
                                      uint32_t& r2, uint32_t& r3) {
    asm volatile("ldmatrix.sync.aligned.m8n8.x4.shared.b16 {%0,%1,%2,%3}, [%4];"
        : "=r"(r0), "=r"(r1), "=r"(r2), "=r"(r3) : "r"(addr));
}

__device__ __forceinline__ void mma16816(float* d, const uint32_t* a,
                                         uint32_t b0, uint32_t b1) {
    asm volatile("mma.sync.aligned.m16n8k16.row.col.f32.bf16.bf16.f32 "
        "{%0,%1,%2,%3}, {%4,%5,%6,%7}, {%8,%9}, {%0,%1,%2,%3};"
        : "+f"(d[0]), "+f"(d[1]), "+f"(d[2]), "+f"(d[3])
        : "r"(a[0]), "r"(a[1]), "r"(a[2]), "r"(a[3]), "r"(b0), "r"(b1));
}

// ------------------------------------------------------------------
// fp32 -> (bf16 hi, bf16 lo) split
// ------------------------------------------------------------------
__global__ void split_kernel(const float* __restrict__ x,
                             __nv_bfloat16* __restrict__ hi,
                             __nv_bfloat16* __restrict__ lo, int n) {
    int i = blockIdx.x * blockDim.x + threadIdx.x;
    if (i >= n) return;
    float v = x[i];
    __nv_bfloat16 h = __float2bfloat16(v);
    float r = v - __bfloat162float(h);
    hi[i] = h;
    lo[i] = __float2bfloat16(r);
}

// ------------------------------------------------------------------
// Bias table
// ------------------------------------------------------------------
__global__ void bias_kernel(const float* __restrict__ rel_bias) {
    int idx = blockIdx.x * blockDim.x + threadIdx.x;
    const int total = (2*SS-1)*HH;
    if (idx >= total) return;
    int d = idx / HH;
    int h = idx - d*HH;
    int rp = d - (SS - 1);
    int rb = (rp > 0) ? 16 : 0;
    int n = rp < 0 ? -rp : rp;
    int b;
    if (n < 8) {
        b = n;
    } else {
        double v = log((double)n / 8.0) / log(16.0) * 8.0;
        int large = 8 + (int)v;
        b = large < 15 ? large : 15;
    }
    g_bias[idx] = rel_bias[(rb + b)*HH + h];
}

// ------------------------------------------------------------------
// HMMA bf16x3 GEMM: C[m,n] = sum_k A[m,k]*W[n,k]
// 128x128 CTA tile, BK=32, 3-stage cp.async pipeline, 8 warps (2x4).
// mode 0: C row-major [4096,1024]; mode 1: head-split.
// ------------------------------------------------------------------
#define BKG 32
#define STAGES 3
#define TENSOR_BYTES (128*64)            // 128 rows x 64B (32 bf16)
#define STAGE_BYTES  (4*TENSOR_BYTES)    // 32 KB
#define GEMM_SMEM    (STAGES*STAGE_BYTES) // 96 KB

__global__ void __launch_bounds__(256) gemm_mma_kernel(
    const __nv_bfloat16* __restrict__ Ahi, const __nv_bfloat16* __restrict__ Alo,
    const __nv_bfloat16* __restrict__ Whi, const __nv_bfloat16* __restrict__ Wlo,
    float* __restrict__ C, int mode)
{
    extern __shared__ __align__(128) char smem[];
    const uint32_t sb = smem_u32(smem);
    const int tid  = threadIdx.x;
    const int warp = tid >> 5, lane = tid & 31;
    const int wm = warp >> 2, wn = warp & 3;
    const int nt = blockIdx.x, mt = blockIdx.y;

    const __nv_bfloat16* src0 = Ahi + (size_t)(mt*128)*1024;
    const __nv_bfloat16* src1 = Alo + (size_t)(mt*128)*1024;
    const __nv_bfloat16* src2 = Whi + (size_t)(nt*128)*1024;
    const __nv_bfloat16* src3 = Wlo + (size_t)(nt*128)*1024;
    const __nv_bfloat16* mysrc = (tid < 64) ? src0 : (tid < 128) ? src1
                               : (tid < 192) ? src2 : src3;
    const int t4 = tid >> 6;
    const int li = tid & 63;

    // issue one stage of global->smem cp.asyncs for K-iteration `it`
    #define ISSUE(it) do { \
        int _stg = (it) % STAGES; \
        uint32_t _sbase = sb + _stg*STAGE_BYTES + t4*TENSOR_BYTES; \
        const __nv_bfloat16* _g = mysrc + (it)*BKG; \
        _Pragma("unroll") \
        for (int _j = 0; _j < 8; _j++) { \
            int _ch = li + _j*64; \
            int _r = _ch >> 2, _c = _ch & 3; \
            int _cs = _c ^ ((_r >> 1) & 3); \
            CP_ASYNC16(_sbase + _r*64 + _cs*16, _g + (size_t)_r*1024 + _c*8); \
        } \
    } while (0)

    ISSUE(0); CP_COMMIT();
    ISSUE(1); CP_COMMIT();

    float acc[4][4][4];
    #pragma unroll
    for (int i = 0; i < 4; i++)
        #pragma unroll
        for (int j = 0; j < 4; j++)
            #pragma unroll
            for (int q = 0; q < 4; q++) acc[i][j][q] = 0.f;

    const int arow = lane & 15;
    const int asel = lane >> 4;
    const int brow = ((lane >> 4) << 3) | (lane & 7);
    const int bsel = (lane >> 3) & 1;

    for (int it = 0; it < 32; it++) {
        CP_WAIT1();
        __syncthreads();
        if (it + 2 < 32) ISSUE(it + 2);
        CP_COMMIT();

        const uint32_t st = sb + (it % STAGES)*STAGE_BYTES;
        #pragma unroll
        for (int ks = 0; ks < 2; ks++) {
            uint32_t ah[4][4], al[4][4];
            #pragma unroll
            for (int mi = 0; mi < 4; mi++) {
                int r = wm*64 + mi*16 + arow;
                int c = 2*ks + asel;
                uint32_t off = (uint32_t)(r*64 + ((c ^ ((r>>1)&3))*16));
                ldsm4(st + off,               ah[mi][0], ah[mi][1], ah[mi][2], ah[mi][3]);
                ldsm4(st + TENSOR_BYTES + off, al[mi][0], al[mi][1], al[mi][2], al[mi][3]);
            }
            uint32_t bh[2][4], bl[2][4];
            #pragma unroll
            for (int np = 0; np < 2; np++) {
                int r = wn*32 + np*16 + brow;
                int c = 2*ks + bsel;
                uint32_t off = (uint32_t)(r*64 + ((c ^ ((r>>1)&3))*16));
                ldsm4(st + 2*TENSOR_BYTES + off, bh[np][0], bh[np][1], bh[np][2], bh[np][3]);
                ldsm4(st + 3*TENSOR_BYTES + off, bl[np][0], bl[np][1], bl[np][2], bl[np][3]);
            }
            #pragma unroll
            for (int mi = 0; mi < 4; mi++)
                #pragma unroll
                for (int ni = 0; ni < 4; ni++) {
                    uint32_t b0h = bh[ni>>1][(ni&1)*2], b1h = bh[ni>>1][(ni&1)*2+1];
                    uint32_t b0l = bl[ni>>1][(ni&1)*2], b1l = bl[ni>>1][(ni&1)*2+1];
                    mma16816(acc[mi][ni], ah[mi], b0h, b1h);
                    mma16816(acc[mi][ni], ah[mi], b0l, b1l);
                    mma16816(acc[mi][ni], al[mi], b0h, b1h);
                }
        }
    }

    // epilogue
    const int mrow0 = mt*128 + wm*64;
    const int ncol0 = nt*128 + wn*32;
    const int lrow = lane >> 2;
    const int lcol = (lane & 3)*2;
    #pragma unroll
    for (int mi = 0; mi < 4; mi++)
        #pragma unroll
        for (int ni = 0; ni < 4; ni++) {
            int m0 = mrow0 + mi*16 + lrow;
            int n0 = ncol0 + ni*8 + lcol;
            float2 v0 = make_float2(acc[mi][ni][0], acc[mi][ni][1]);
            float2 v1 = make_float2(acc[mi][ni][2], acc[mi][ni][3]);
            if (mode == 0) {
                *(float2*)(C + (size_t)m0*1024 + n0)     = v0;
                *(float2*)(C + (size_t)(m0+8)*1024 + n0) = v1;
            } else {
                int h = n0 >> 6, dk = n0 & 63;
                int b0 = m0 >> 10, s0 = m0 & 1023;
                int b1 = (m0+8) >> 10, s1 = (m0+8) & 1023;
                *(float2*)(C + ((size_t)((b0*HH + h)*SS + s0))*DKK + dk) = v0;
                *(float2*)(C + ((size_t)((b1*HH + h)*SS + s1))*DKK + dk) = v1;
            }
        }
}

// ------------------------------------------------------------------
// Scores: per (b,h): S[m,n] = Q[m,:] . K[n,:] + bias(n-m, h)
// ------------------------------------------------------------------
__global__ void __launch_bounds__(256) scores_kernel() {
    __shared__ __align__(16) float Qs[64][68];
    __shared__ __align__(16) float Ks[64][68];

    const int tid = threadIdx.x;
    const int bh = blockIdx.z;
    const int h  = bh & (HH-1);
    const int mbase = blockIdx.y * 64;
    const int nbase = blockIdx.x * 64;

    const float* Q = g_q + (size_t)bh*SS*DKK + (size_t)mbase*DKK;
    const float* K = g_k + (size_t)bh*SS*DKK + (size_t)nbase*DKK;

    for (int i = tid; i < 64*16; i += 256) {
        int r  = i >> 4;
        int kc = (i & 15) << 2;
        float4 q = *(const float4*)(Q + r*DKK + kc);
        Qs[kc+0][r] = q.x; Qs[kc+1][r] = q.y; Qs[kc+2][r] = q.z; Qs[kc+3][r] = q.w;
        float4 k = *(const float4*)(K + r*DKK + kc);
        Ks[kc+0][r] = k.x; Ks[kc+1][r] = k.y; Ks[kc+2][r] = k.z; Ks[kc+3][r] = k.w;
    }
    __syncthreads();

    const int tx = tid & 15, ty = tid >> 4;
    const int m0 = ty*4, n0 = tx*4;

    float acc[4][4];
    #pragma unroll
    for (int i = 0; i < 4; i++)
        #pragma unroll
        for (int j = 0; j < 4; j++) acc[i][j] = 0.f;

    #pragma unroll 8
    for (int k = 0; k < 64; k++) {
        float4 q4 = *(const float4*)&Qs[k][m0];
        float4 k4 = *(const float4*)&Ks[k][n0];
        float qa[4] = {q4.x, q4.y, q4.z, q4.w};
        float ka[4] = {k4.x, k4.y, k4.z, k4.w};
        #pragma unroll
        for (int i = 0; i < 4; i++)
            #pragma unroll
            for (int j = 0; j < 4; j++)
                acc[i][j] = fmaf(qa[i], ka[j], acc[i][j]);
    }

    #pragma unroll
    for (int i = 0; i < 4; i++) {
        int mg = mbase + m0 + i;
        int ng = nbase + n0;
        const float* bt = g_bias + (size_t)(ng - mg + (SS-1))*HH + h;
        float4 o;
        o.x = acc[i][0] + bt[0*HH];
        o.y = acc[i][1] + bt[1*HH];
        o.z = acc[i][2] + bt[2*HH];
        o.w = acc[i][3] + bt[3*HH];
        *(float4*)&g_scores[((size_t)bh*SS + mg)*SS + ng] = o;
    }
}

// ------------------------------------------------------------------
__global__ void __launch_bounds__(256) softmax_kernel() {
    __shared__ float redm[8];
    __shared__ float reds[8];
    size_t row = blockIdx.x;
    float* p = g_scores + row * SS;
    int t = threadIdx.x;
    int lane = t & 31, wid = t >> 5;

    float4 v = ((const float4*)p)[t];
    float m = fmaxf(fmaxf(v.x, v.y), fmaxf(v.z, v.w));
    #pragma unroll
    for (int o = 16; o; o >>= 1) m = fmaxf(m, __shfl_xor_sync(0xffffffffu, m, o));
    if (lane == 0) redm[wid] = m;
    __syncthreads();
    m = redm[0];
    #pragma unroll
    for (int i = 1; i < 8; i++) m = fmaxf(m, redm[i]);

    v.x = expf(v.x - m); v.y = expf(v.y - m);
    v.z = expf(v.z - m); v.w = expf(v.w - m);
    float s = v.x + v.y + v.z + v.w;
    #pragma unroll
    for (int o = 16; o; o >>= 1) s += __shfl_xor_sync(0xffffffffu, s, o);
    if (lane == 0) reds[wid] = s;
    __syncthreads();
    s = reds[0];
    #pragma unroll
    for (int i = 1; i < 8; i++) s += reds[i];

    float inv = 1.0f / s;
    v.x *= inv; v.y *= inv; v.z *= inv; v.w *= inv;
    ((float4*)p)[t] = v;
}

// ------------------------------------------------------------------
__global__ void __launch_bounds__(256) ctx_kernel() {
    __shared__ __align__(16) float Ps[64][68];
    __shared__ __align__(16) float Vs[64][68];

    const int tid = threadIdx.x;
    const int bh = blockIdx.y;
    const int mbase = blockIdx.x * 64;
    const int b = bh >> 4, h = bh & 15;

    const int tx = tid & 15, ty = tid >> 4;
    const int m0 = ty*4, n0 = tx*4;

    float acc[4][4];
    #pragma unroll
    for (int i = 0; i < 4; i++)
        #pragma unroll
        for (int j = 0; j < 4; j++) acc[i][j] = 0.f;

    for (int kt = 0; kt < SS; kt += 64) {
        __syncthreads();
        for (int i = tid; i < 64*16; i += 256) {
            int r  = i >> 4;
            int kc = (i & 15) << 2;
            float4 pv = *(const float4*)(g_scores + ((size_t)bh*SS + mbase + r)*SS + kt + kc);
            Ps[kc+0][r] = pv.x; Ps[kc+1][r] = pv.y; Ps[kc+2][r] = pv.z; Ps[kc+3][r] = pv.w;
            float4 vv = *(const float4*)(g_v + ((size_t)bh*SS + kt + r)*DKK + kc);
            *(float4*)&Vs[r][kc] = vv;
        }
        __syncthreads();
        #pragma unroll 8
        for (int k = 0; k < 64; k++) {
            float4 p4 = *(const float4*)&Ps[k][m0];
            float4 v4 = *(const float4*)&Vs[k][n0];
            float pa[4] = {p4.x, p4.y, p4.z, p4.w};
            float va[4] = {v4.x, v4.y, v4.z, v4.w};
            #pragma unroll
            for (int i = 0; i < 4; i++)
                #pragma unroll
                for (int j = 0; j < 4; j++)
                    acc[i][j] = fmaf(pa[i], va[j], acc[i][j]);
        }
    }

    #pragma unroll
    for (int i = 0; i < 4; i++) {
        int s = mbase + m0 + i;
        float* dst = g_ctx + ((size_t)(b*SS + s))*DD + h*DKK + n0;
        *(float4*)dst = make_float4(acc[i][0], acc[i][1], acc[i][2], acc[i][3]);
    }
}

// ------------------------------------------------------------------
extern "C" void kernel_launch(void* const* d_in, const int* in_sizes, int n_in,
                              void* d_out, int out_size) {
    const float* hidden   = (const float*)d_in[0];
    const float* Wq       = (const float*)d_in[1];
    const float* Wk       = (const float*)d_in[2];
    const float* Wv       = (const float*)d_in[3];
    const float* Wo       = (const float*)d_in[4];
    const float* rel_bias = (const float*)d_in[5];
    float* out = (float*)d_out;

    float *pq, *pk, *pv, *pctx;
    __nv_bfloat16 *pahi, *palo, *pwhi, *pwlo;
    cudaGetSymbolAddress((void**)&pq,   g_q);
    cudaGetSymbolAddress((void**)&pk,   g_k);
    cudaGetSymbolAddress((void**)&pv,   g_v);
    cudaGetSymbolAddress((void**)&pctx, g_ctx);
    cudaGetSymbolAddress((void**)&pahi, g_ahi);
    cudaGetSymbolAddress((void**)&palo, g_alo);
    cudaGetSymbolAddress((void**)&pwhi, g_whi);
    cudaGetSymbolAddress((void**)&pwlo, g_wlo);

    cudaFuncSetAttribute(gemm_mma_kernel,
                         cudaFuncAttributeMaxDynamicSharedMemorySize, GEMM_SMEM);

    const int nA = 4096*1024;
    const int nW = 1024*1024;

    // 1. bias table
    bias_kernel<<<((2*SS-1)*HH + 255)/256, 256>>>(rel_bias);

    // 2. split hidden
    split_kernel<<<(nA + 255)/256, 256>>>(hidden, pahi, palo, nA);

    // 3. QKV projections via HMMA bf16x3 (head-split output)
    dim3 ggrid(8, 32);
    split_kernel<<<(nW + 255)/256, 256>>>(Wq, pwhi, pwlo, nW);
    gemm_mma_kernel<<<ggrid, 256, GEMM_SMEM>>>(pahi, palo, pwhi, pwlo, pq, 1);
    split_kernel<<<(nW + 255)/256, 256>>>(Wk, pwhi, pwlo, nW);
    gemm_mma_kernel<<<ggrid, 256, GEMM_SMEM>>>(pahi, palo, pwhi, pwlo, pk, 1);
    split_kernel<<<(nW + 255)/256, 256>>>(Wv, pwhi, pwlo, nW);
    gemm_mma_kernel<<<ggrid, 256, GEMM_SMEM>>>(pahi, palo, pwhi, pwlo, pv, 1);

    // 4. scores + bias
    scores_kernel<<<dim3(16, 16, BH), 256>>>();
    // 5. softmax
    softmax_kernel<<<BH*SS, 256>>>();
    // 6. ctx = P @ V
    ctx_kernel<<<dim3(16, BH), 256>>>();

    // 7. output projection (reuse A-split buffers for ctx)
    split_kernel<<<(nA + 255)/256, 256>>>(pctx, pahi, palo, nA);
    split_kernel<<<(nW + 255)/256, 256>>>(Wo, pwhi, pwlo, nW);
    gemm_mma_kernel<<<ggrid, 256, GEMM_SMEM>>>(pahi, palo, pwhi, pwlo, out, 0);
}

// round 4
// speedup vs baseline: 3.1216x; 2.1064x over previous
#include <cuda_runtime.h>
#include <cuda_bf16.h>
#include <math.h>
#include <stdint.h>

#define BB 4
#define SS 1024
#define DD 1024
#define HH 16
#define DKK 64
#define BH (BB*HH)

// ---- scratch (device globals; no allocation allowed) ----
__device__ float g_q[BH*SS*DKK];        // 16 MB  [b,h,s,dk]
__device__ float g_k[BH*SS*DKK];        // 16 MB
__device__ float g_v[BH*SS*DKK];        // 16 MB
__device__ float g_ctx[BB*SS*DD];       // 16 MB  [b,s,h*dk]
__device__ float g_bias[(2*SS-1)*HH];   // bias by delta = k - q

// bf16x3 split buffers (16B aligned for cp.async)
__device__ __align__(16) __nv_bfloat16 g_ahi[4096*1024];
__device__ __align__(16) __nv_bfloat16 g_alo[4096*1024];
__device__ __align__(16) __nv_bfloat16 g_whi[1024*1024];
__device__ __align__(16) __nv_bfloat16 g_wlo[1024*1024];

// ================= PTX helpers (baseline ISA only) =================
__device__ __forceinline__ uint32_t smem_u32(const void* p) {
    uint32_t a;
    asm("{ .reg .u64 t; cvta.to.shared.u64 t, %1; cvt.u32.u64 %0, t; }"
        : "=r"(a) : "l"(p));
    return a;
}

#define CP_ASYNC16(sa, ga) \
    asm volatile("cp.async.cg.shared.global [%0], [%1], 16;" \
        :: "r"(sa), "l"(ga) : "memory")
#define CP_COMMIT() asm volatile("cp.async.commit_group;" ::: "memory")
#define CP_WAIT1()  asm volatile("cp.async.wait_group 1;" ::: "memory")

__device__ __forceinline__ void ldsm4(uint32_t addr, uint32_t& r0, uint32_t& r1,
                                      uint32_t& r2, uint32_t& r3) {
    asm volatile("ldmatrix.sync.aligned.m8n8.x4.shared.b16 {%0,%1,%2,%3}, [%4];"
        : "=r"(r0), "=r"(r1), "=r"(r2), "=r"(r3) : "r"(addr));
}
__device__ __forceinline__ void ldsm4t(uint32_t addr, uint32_t& r0, uint32_t& r1,
                                       uint32_t& r2, uint32_t& r3) {
    asm volatile("ldmatrix.sync.aligned.m8n8.x4.trans.shared.b16 {%0,%1,%2,%3}, [%4];"
        : "=r"(r0), "=r"(r1), "=r"(r2), "=r"(r3) : "r"(addr));
}

__device__ __forceinline__ void mma16816(float* d, const uint32_t* a,
                                         uint32_t b0, uint32_t b1) {
    asm volatile("mma.sync.aligned.m16n8k16.row.col.f32.bf16.bf16.f32 "
        "{%0,%1,%2,%3}, {%4,%5,%6,%7}, {%8,%9}, {%0,%1,%2,%3};"
        : "+f"(d[0]), "+f"(d[1]), "+f"(d[2]), "+f"(d[3])
        : "r"(a[0]), "r"(a[1]), "r"(a[2]), "r"(a[3]), "r"(b0), "r"(b1));
}

__device__ __forceinline__ uint32_t packbf2(float a, float b) {
    __nv_bfloat162 t = __floats2bfloat162_rn(a, b);
    return *(uint32_t*)&t;
}

// ------------------------------------------------------------------
__global__ void split_kernel(const float* __restrict__ x,
                             __nv_bfloat16* __restrict__ hi,
                             __nv_bfloat16* __restrict__ lo, int n) {
    int i = blockIdx.x * blockDim.x + threadIdx.x;
    if (i >= n) return;
    float v = x[i];
    __nv_bfloat16 h = __float2bfloat16(v);
    float r = v - __bfloat162float(h);
    hi[i] = h;
    lo[i] = __float2bfloat16(r);
}

// ------------------------------------------------------------------
__global__ void bias_kernel(const float* __restrict__ rel_bias) {
    int idx = blockIdx.x * blockDim.x + threadIdx.x;
    const int total = (2*SS-1)*HH;
    if (idx >= total) return;
    int d = idx / HH;
    int h = idx - d*HH;
    int rp = d - (SS - 1);
    int rb = (rp > 0) ? 16 : 0;
    int n = rp < 0 ? -rp : rp;
    int b;
    if (n < 8) {
        b = n;
    } else {
        double v = log((double)n / 8.0) / log(16.0) * 8.0;
        int large = 8 + (int)v;
        b = large < 15 ? large : 15;
    }
    g_bias[idx] = rel_bias[(rb + b)*HH + h];
}

// ------------------------------------------------------------------
// HMMA bf16x3 GEMM (unchanged from round 3)
// ------------------------------------------------------------------
#define BKG 32
#define STAGES 3
#define TENSOR_BYTES (128*64)
#define STAGE_BYTES  (4*TENSOR_BYTES)
#define GEMM_SMEM    (STAGES*STAGE_BYTES)

__global__ void __launch_bounds__(256) gemm_mma_kernel(
    const __nv_bfloat16* __restrict__ Ahi, const __nv_bfloat16* __restrict__ Alo,
    const __nv_bfloat16* __restrict__ Whi, const __nv_bfloat16* __restrict__ Wlo,
    float* __restrict__ C, int mode)
{
    extern __shared__ __align__(128) char smem[];
    const uint32_t sb = smem_u32(smem);
    const int tid  = threadIdx.x;
    const int warp = tid >> 5, lane = tid & 31;
    const int wm = warp >> 2, wn = warp & 3;
    const int nt = blockIdx.x, mt = blockIdx.y;

    const __nv_bfloat16* src0 = Ahi + (size_t)(mt*128)*1024;
    const __nv_bfloat16* src1 = Alo + (size_t)(mt*128)*1024;
    const __nv_bfloat16* src2 = Whi + (size_t)(nt*128)*1024;
    const __nv_bfloat16* src3 = Wlo + (size_t)(nt*128)*1024;
    const __nv_bfloat16* mysrc = (tid < 64) ? src0 : (tid < 128) ? src1
                               : (tid < 192) ? src2 : src3;
    const int t4 = tid >> 6;
    const int li = tid & 63;

    #define ISSUE(it) do { \
        int _stg = (it) % STAGES; \
        uint32_t _sbase = sb + _stg*STAGE_BYTES + t4*TENSOR_BYTES; \
        const __nv_bfloat16* _g = mysrc + (it)*BKG; \
        _Pragma("unroll") \
        for (int _j = 0; _j < 8; _j++) { \
            int _ch = li + _j*64; \
            int _r = _ch >> 2, _c = _ch & 3; \
            int _cs = _c ^ ((_r >> 1) & 3); \
            CP_ASYNC16(_sbase + _r*64 + _cs*16, _g + (size_t)_r*1024 + _c*8); \
        } \
    } while (0)

    ISSUE(0); CP_COMMIT();
    ISSUE(1); CP_COMMIT();

    float acc[4][4][4];
    #pragma unroll
    for (int i = 0; i < 4; i++)
        #pragma unroll
        for (int j = 0; j < 4; j++)
            #pragma unroll
            for (int q = 0; q < 4; q++) acc[i][j][q] = 0.f;

    const int arow = lane & 15;
    const int asel = lane >> 4;
    const int brow = ((lane >> 4) << 3) | (lane & 7);
    const int bsel = (lane >> 3) & 1;

    for (int it = 0; it < 32; it++) {
        CP_WAIT1();
        __syncthreads();
        if (it + 2 < 32) ISSUE(it + 2);
        CP_COMMIT();

        const uint32_t st = sb + (it % STAGES)*STAGE_BYTES;
        #pragma unroll
        for (int ks = 0; ks < 2; ks++) {
            uint32_t ah[4][4], al[4][4];
            #pragma unroll
            for (int mi = 0; mi < 4; mi++) {
                int r = wm*64 + mi*16 + arow;
                int c = 2*ks + asel;
                uint32_t off = (uint32_t)(r*64 + ((c ^ ((r>>1)&3))*16));
                ldsm4(st + off,               ah[mi][0], ah[mi][1], ah[mi][2], ah[mi][3]);
                ldsm4(st + TENSOR_BYTES + off, al[mi][0], al[mi][1], al[mi][2], al[mi][3]);
            }
            uint32_t bh2[2][4], bl2[2][4];
            #pragma unroll
            for (int np = 0; np < 2; np++) {
                int r = wn*32 + np*16 + brow;
                int c = 2*ks + bsel;
                uint32_t off = (uint32_t)(r*64 + ((c ^ ((r>>1)&3))*16));
                ldsm4(st + 2*TENSOR_BYTES + off, bh2[np][0], bh2[np][1], bh2[np][2], bh2[np][3]);
                ldsm4(st + 3*TENSOR_BYTES + off, bl2[np][0], bl2[np][1], bl2[np][2], bl2[np][3]);
            }
            #pragma unroll
            for (int mi = 0; mi < 4; mi++)
                #pragma unroll
                for (int ni = 0; ni < 4; ni++) {
                    uint32_t b0h = bh2[ni>>1][(ni&1)*2], b1h = bh2[ni>>1][(ni&1)*2+1];
                    uint32_t b0l = bl2[ni>>1][(ni&1)*2], b1l = bl2[ni>>1][(ni&1)*2+1];
                    mma16816(acc[mi][ni], ah[mi], b0h, b1h);
                    mma16816(acc[mi][ni], ah[mi], b0l, b1l);
                    mma16816(acc[mi][ni], al[mi], b0h, b1h);
                }
        }
    }
    #undef ISSUE

    const int mrow0 = mt*128 + wm*64;
    const int ncol0 = nt*128 + wn*32;
    const int lrow = lane >> 2;
    const int lcol = (lane & 3)*2;
    #pragma unroll
    for (int mi = 0; mi < 4; mi++)
        #pragma unroll
        for (int ni = 0; ni < 4; ni++) {
            int m0 = mrow0 + mi*16 + lrow;
            int n0 = ncol0 + ni*8 + lcol;
            float2 v0 = make_float2(acc[mi][ni][0], acc[mi][ni][1]);
            float2 v1 = make_float2(acc[mi][ni][2], acc[mi][ni][3]);
            if (mode == 0) {
                *(float2*)(C + (size_t)m0*1024 + n0)     = v0;
                *(float2*)(C + (size_t)(m0+8)*1024 + n0) = v1;
            } else {
                int h = n0 >> 6, dk = n0 & 63;
                int b0 = m0 >> 10, s0 = m0 & 1023;
                int b1 = (m0+8) >> 10, s1 = (m0+8) & 1023;
                *(float2*)(C + ((size_t)((b0*HH + h)*SS + s0))*DKK + dk) = v0;
                *(float2*)(C + ((size_t)((b1*HH + h)*SS + s1))*DKK + dk) = v1;
            }
        }
}

// ------------------------------------------------------------------
// Fused flash attention: per (qtile, bh). Q tile 128 rows, loop 8 KV tiles.
// bf16x3 HMMA for QK^T and PV. Online softmax. Bias from smem window.
// ------------------------------------------------------------------
#define T16K 16384
#define OFF_QH 0
#define OFF_QL (1*T16K)
#define OFF_KH (2*T16K)
#define OFF_KL (3*T16K)
#define OFF_VH (4*T16K)
#define OFF_VL (5*T16K)
#define OFF_BIAS (6*T16K)
#define FLASH_SMEM (6*T16K + 1024)

// swizzled byte offset in a [row][64 bf16] tile (128B rows, 8 chunks of 16B)
#define SWZ(r, c) ((uint32_t)((r)*128 + (((c) ^ ((r)&7))*16)))

// convert one 128x64 fp32 tile (row stride 64) to bf16 hi/lo swizzled smem
__device__ __forceinline__ void conv_tile(const float* __restrict__ g,
                                          char* hi, char* lo, int tid) {
    #pragma unroll
    for (int i = 0; i < 4; i++) {
        int idx = tid + i*256;
        int r = idx >> 3, c = idx & 7;
        const float* src = g + (size_t)r*64 + c*8;
        float4 f0 = *(const float4*)(src);
        float4 f1 = *(const float4*)(src + 4);
        uint4 h, l;
        __nv_bfloat16 b;
        float vv;
        #define CVT(outh, outl, x0, x1) do { \
            __nv_bfloat16 h0 = __float2bfloat16(x0); \
            __nv_bfloat16 h1 = __float2bfloat16(x1); \
            float l0 = (x0) - __bfloat162float(h0); \
            float l1 = (x1) - __bfloat162float(h1); \
            __nv_bfloat162 th; th.x = h0; th.y = h1; \
            outh = *(uint32_t*)&th; \
            __nv_bfloat162 tl; tl.x = __float2bfloat16(l0); tl.y = __float2bfloat16(l1); \
            outl = *(uint32_t*)&tl; \
        } while (0)
        CVT(h.x, l.x, f0.x, f0.y);
        CVT(h.y, l.y, f0.z, f0.w);
        CVT(h.z, l.z, f1.x, f1.y);
        CVT(h.w, l.w, f1.z, f1.w);
        #undef CVT
        (void)b; (void)vv;
        uint32_t off = SWZ(r, c);
        *(uint4*)(hi + off) = h;
        *(uint4*)(lo + off) = l;
    }
}

__global__ void __launch_bounds__(256, 1) flash_kernel() {
    extern __shared__ __align__(128) char smem[];
    const uint32_t sb = smem_u32(smem);
    float* bias_s = (float*)(smem + OFF_BIAS);

    const int tid  = threadIdx.x;
    const int w = tid >> 5, lane = tid & 31;
    const int mbase = blockIdx.x * 128;
    const int bh = blockIdx.y;
    const int b = bh >> 4, h = bh & 15;

    const float* Qg = g_q + (size_t)bh*SS*DKK + (size_t)mbase*DKK;
    const float* Kg = g_k + (size_t)bh*SS*DKK;
    const float* Vg = g_v + (size_t)bh*SS*DKK;

    conv_tile(Qg, smem + OFF_QH, smem + OFF_QL, tid);

    float Oacc[8][4];
    #pragma unroll
    for (int d = 0; d < 8; d++)
        #pragma unroll
        for (int q = 0; q < 4; q++) Oacc[d][q] = 0.f;
    float mrun0 = -1e30f, mrun1 = -1e30f, lrun0 = 0.f, lrun1 = 0.f;

    const int r0 = lane >> 2;
    const int colb = (lane & 3)*2;
    const int rl0 = w*16 + r0;
    const int rl1 = rl0 + 8;

    // fragment addresses
    const int a_r = w*16 + (lane & 15);
    const int a_s = lane >> 4;
    const int b_r = ((lane >> 4) << 3) | (lane & 7);
    const int b_s = (lane >> 3) & 1;
    const int v_k = ((lane >> 3) & 1)*8 + (lane & 7);
    const int v_c = lane >> 4;

    for (int j = 0; j < 8; j++) {
        __syncthreads();   // protect K/V smem reuse
        conv_tile(Kg + (size_t)j*128*64, smem + OFF_KH, smem + OFF_KL, tid);
        conv_tile(Vg + (size_t)j*128*64, smem + OFF_VH, smem + OFF_VL, tid);
        {
            int t = tid;
            if (t < 255) {
                int delta = j*128 - mbase + (t - 127);
                bias_s[t] = g_bias[(size_t)(delta + SS - 1)*HH + h];
            }
        }
        __syncthreads();

        // ---- S = Q K^T (bf16x3) ----
        float sacc[16][4];
        #pragma unroll
        for (int nt = 0; nt < 16; nt++)
            #pragma unroll
            for (int q = 0; q < 4; q++) sacc[nt][q] = 0.f;

        #pragma unroll
        for (int ks = 0; ks < 4; ks++) {
            uint32_t aqh[4], aql[4];
            uint32_t aoff = SWZ(a_r, 2*ks + a_s);
            ldsm4(sb + OFF_QH + aoff, aqh[0], aqh[1], aqh[2], aqh[3]);
            ldsm4(sb + OFF_QL + aoff, aql[0], aql[1], aql[2], aql[3]);
            #pragma unroll
            for (int np = 0; np < 8; np++) {
                uint32_t kh[4], kl[4];
                uint32_t boff = SWZ(np*16 + b_r, 2*ks + b_s);
                ldsm4(sb + OFF_KH + boff, kh[0], kh[1], kh[2], kh[3]);
                ldsm4(sb + OFF_KL + boff, kl[0], kl[1], kl[2], kl[3]);
                mma16816(sacc[2*np],   aqh, kh[0], kh[1]);
                mma16816(sacc[2*np],   aqh, kl[0], kl[1]);
                mma16816(sacc[2*np],   aql, kh[0], kh[1]);
                mma16816(sacc[2*np+1], aqh, kh[2], kh[3]);
                mma16816(sacc[2*np+1], aqh, kl[2], kl[3]);
                mma16816(sacc[2*np+1], aql, kh[2], kh[3]);
            }
        }

        // ---- bias ----
        #pragma unroll
        for (int nt = 0; nt < 16; nt++) {
            int col = nt*8 + colb;
            sacc[nt][0] += bias_s[col     - rl0 + 127];
            sacc[nt][1] += bias_s[col + 1 - rl0 + 127];
            sacc[nt][2] += bias_s[col     - rl1 + 127];
            sacc[nt][3] += bias_s[col + 1 - rl1 + 127];
        }

        // ---- online softmax ----
        float mx0 = -1e30f, mx1 = -1e30f;
        #pragma unroll
        for (int nt = 0; nt < 16; nt++) {
            mx0 = fmaxf(mx0, fmaxf(sacc[nt][0], sacc[nt][1]));
            mx1 = fmaxf(mx1, fmaxf(sacc[nt][2], sacc[nt][3]));
        }
        mx0 = fmaxf(mx0, __shfl_xor_sync(0xffffffffu, mx0, 1));
        mx0 = fmaxf(mx0, __shfl_xor_sync(0xffffffffu, mx0, 2));
        mx1 = fmaxf(mx1, __shfl_xor_sync(0xffffffffu, mx1, 1));
        mx1 = fmaxf(mx1, __shfl_xor_sync(0xffffffffu, mx1, 2));

        float mn0 = fmaxf(mrun0, mx0);
        float mn1 = fmaxf(mrun1, mx1);
        float al0 = __expf(mrun0 - mn0);
        float al1 = __expf(mrun1 - mn1);
        mrun0 = mn0; mrun1 = mn1;

        float rs0 = 0.f, rs1 = 0.f;
        #pragma unroll
        for (int nt = 0; nt < 16; nt++) {
            sacc[nt][0] = __expf(sacc[nt][0] - mn0);
            sacc[nt][1] = __expf(sacc[nt][1] - mn0);
            sacc[nt][2] = __expf(sacc[nt][2] - mn1);
            sacc[nt][3] = __expf(sacc[nt][3] - mn1);
            rs0 += sacc[nt][0] + sacc[nt][1];
            rs1 += sacc[nt][2] + sacc[nt][3];
        }
        rs0 += __shfl_xor_sync(0xffffffffu, rs0, 1);
        rs0 += __shfl_xor_sync(0xffffffffu, rs0, 2);
        rs1 += __shfl_xor_sync(0xffffffffu, rs1, 1);
        rs1 += __shfl_xor_sync(0xffffffffu, rs1, 2);
        lrun0 = lrun0*al0 + rs0;
        lrun1 = lrun1*al1 + rs1;

        #pragma unroll
        for (int d = 0; d < 8; d++) {
            Oacc[d][0] *= al0; Oacc[d][1] *= al0;
            Oacc[d][2] *= al1; Oacc[d][3] *= al1;
        }

        // ---- O += P V (bf16x3, P from registers) ----
        #pragma unroll
        for (int ks = 0; ks < 8; ks++) {
            uint32_t ph[4], pl[4];
            {
                float p00 = sacc[2*ks][0],   p01 = sacc[2*ks][1];
                float p02 = sacc[2*ks][2],   p03 = sacc[2*ks][3];
                float p10 = sacc[2*ks+1][0], p11 = sacc[2*ks+1][1];
                float p12 = sacc[2*ks+1][2], p13 = sacc[2*ks+1][3];
                ph[0] = packbf2(p00, p01);
                ph[1] = packbf2(p02, p03);
                ph[2] = packbf2(p10, p11);
                ph[3] = packbf2(p12, p13);
                __nv_bfloat162* hp = (__nv_bfloat162*)ph;
                pl[0] = packbf2(p00 - __bfloat162float(hp[0].x), p01 - __bfloat162float(hp[0].y));
                pl[1] = packbf2(p02 - __bfloat162float(hp[1].x), p03 - __bfloat162float(hp[1].y));
                pl[2] = packbf2(p10 - __bfloat162float(hp[2].x), p11 - __bfloat162float(hp[2].y));
                pl[3] = packbf2(p12 - __bfloat162float(hp[3].x), p13 - __bfloat162float(hp[3].y));
            }
            #pragma unroll
            for (int dp = 0; dp < 4; dp++) {
                uint32_t vh[4], vl[4];
                uint32_t voff = SWZ(ks*16 + v_k, dp*2 + v_c);
                ldsm4t(sb + OFF_VH + voff, vh[0], vh[1], vh[2], vh[3]);
                ldsm4t(sb + OFF_VL + voff, vl[0], vl[1], vl[2], vl[3]);
                mma16816(Oacc[2*dp],   ph, vh[0], vh[1]);
                mma16816(Oacc[2*dp],   ph, vl[0], vl[1]);
                mma16816(Oacc[2*dp],   pl, vh[0], vh[1]);
                mma16816(Oacc[2*dp+1], ph, vh[2], vh[3]);
                mma16816(Oacc[2*dp+1], ph, vl[2], vl[3]);
                mma16816(Oacc[2*dp+1], pl, vh[2], vh[3]);
            }
        }
    }

    // ---- epilogue: normalize + write [b, s, h*64+d] ----
    float inv0 = 1.0f / lrun0;
    float inv1 = 1.0f / lrun1;
    int m0 = mbase + rl0;
    int m1 = mbase + rl1;
    #pragma unroll
    for (int dt = 0; dt < 8; dt++) {
        int d = dt*8 + colb;
        float2 v0 = make_float2(Oacc[dt][0]*inv0, Oacc[dt][1]*inv0);
        float2 v1 = make_float2(Oacc[dt][2]*inv1, Oacc[dt][3]*inv1);
        *(float2*)(g_ctx + ((size_t)(b*SS + m0))*DD + h*DKK + d) = v0;
        *(float2*)(g_ctx + ((size_t)(b*SS + m1))*DD + h*DKK + d) = v1;
    }
}

// ------------------------------------------------------------------
extern "C" void kernel_launch(void* const* d_in, const int* in_sizes, int n_in,
                              void* d_out, int out_size) {
    const float* hidden   = (const float*)d_in[0];
    const float* Wq       = (const float*)d_in[1];
    const float* Wk       = (const float*)d_in[2];
    const float* Wv       = (const float*)d_in[3];
    const float* Wo       = (const float*)d_in[4];
    const float* rel_bias = (const float*)d_in[5];
    float* out = (float*)d_out;

    float *pq, *pk, *pv, *pctx;
    __nv_bfloat16 *pahi, *palo, *pwhi, *pwlo;
    cudaGetSymbolAddress((void**)&pq,   g_q);
    cudaGetSymbolAddress((void**)&pk,   g_k);
    cudaGetSymbolAddress((void**)&pv,   g_v);
    cudaGetSymbolAddress((void**)&pctx, g_ctx);
    cudaGetSymbolAddress((void**)&pahi, g_ahi);
    cudaGetSymbolAddress((void**)&palo, g_alo);
    cudaGetSymbolAddress((void**)&pwhi, g_whi);
    cudaGetSymbolAddress((void**)&pwlo, g_wlo);

    cudaFuncSetAttribute(gemm_mma_kernel,
                         cudaFuncAttributeMaxDynamicSharedMemorySize, GEMM_SMEM);
    cudaFuncSetAttribute(flash_kernel,
                         cudaFuncAttributeMaxDynamicSharedMemorySize, FLASH_SMEM);

    const int nA = 4096*1024;
    const int nW = 1024*1024;

    bias_kernel<<<((2*SS-1)*HH + 255)/256, 256>>>(rel_bias);
    split_kernel<<<(nA + 255)/256, 256>>>(hidden, pahi, palo, nA);

    dim3 ggrid(8, 32);
    split_kernel<<<(nW + 255)/256, 256>>>(Wq, pwhi, pwlo, nW);
    gemm_mma_kernel<<<ggrid, 256, GEMM_SMEM>>>(pahi, palo, pwhi, pwlo, pq, 1);
    split_kernel<<<(nW + 255)/256, 256>>>(Wk, pwhi, pwlo, nW);
    gemm_mma_kernel<<<ggrid, 256, GEMM_SMEM>>>(pahi, palo, pwhi, pwlo, pk, 1);
    split_kernel<<<(nW + 255)/256, 256>>>(Wv, pwhi, pwlo, nW);
    gemm_mma_kernel<<<ggrid, 256, GEMM_SMEM>>>(pahi, palo, pwhi, pwlo, pv, 1);

    // fused attention
    flash_kernel<<<dim3(8, BH), 256, FLASH_SMEM>>>();

    // output projection
    split_kernel<<<(nA + 255)/256, 256>>>(pctx, pahi, palo, nA);
    split_kernel<<<(nW + 255)/256, 256>>>(Wo, pwhi, pwlo, nW);
    gemm_mma_kernel<<<ggrid, 256, GEMM_SMEM>>>(pahi, palo, pwhi, pwlo, out, 0);
}

// round 5
// speedup vs baseline: 3.5445x; 1.1355x over previous
#include <cuda_runtime.h>
#include <cuda_bf16.h>
#include <math.h>
#include <stdint.h>

#define BB 4
#define SS 1024
#define DD 1024
#define HH 16
#define DKK 64
#define BH (BB*HH)

// ---- scratch (device globals; no allocation allowed) ----
__device__ float g_bias[(2*SS-1)*HH];

// split buffers (16B aligned for cp.async)
__device__ __align__(16) __nv_bfloat16 g_ahi[4096*1024];     // hidden hi
__device__ __align__(16) __nv_bfloat16 g_alo[4096*1024];     // hidden lo
__device__ __align__(16) __nv_bfloat16 g_whi[4096*1024];     // Wq|Wk|Wv|Wo hi (rows 0..4095)
__device__ __align__(16) __nv_bfloat16 g_wlo[4096*1024];     // lo
__device__ __align__(16) __nv_bfloat16 g_qkv_hi[3*4194304];  // q|k|v hi [t][bh][s][dk]
__device__ __align__(16) __nv_bfloat16 g_qkv_lo[3*4194304];
__device__ __align__(16) __nv_bfloat16 g_ctx_hi[4096*1024];  // ctx hi [b*s][h*dk]
__device__ __align__(16) __nv_bfloat16 g_ctx_lo[4096*1024];

// ================= PTX helpers (baseline ISA only) =================
__device__ __forceinline__ uint32_t smem_u32(const void* p) {
    uint32_t a;
    asm("{ .reg .u64 t; cvta.to.shared.u64 t, %1; cvt.u32.u64 %0, t; }"
        : "=r"(a) : "l"(p));
    return a;
}

#define CP_ASYNC16(sa, ga) \
    asm volatile("cp.async.cg.shared.global [%0], [%1], 16;" \
        :: "r"(sa), "l"(ga) : "memory")
#define CP_COMMIT() asm volatile("cp.async.commit_group;" ::: "memory")
#define CP_WAIT1()  asm volatile("cp.async.wait_group 1;" ::: "memory")
#define CP_WAIT0()  asm volatile("cp.async.wait_group 0;" ::: "memory")

__device__ __forceinline__ void ldsm4(uint32_t addr, uint32_t& r0, uint32_t& r1,
                                      uint32_t& r2, uint32_t& r3) {
    asm volatile("ldmatrix.sync.aligned.m8n8.x4.shared.b16 {%0,%1,%2,%3}, [%4];"
        : "=r"(r0), "=r"(r1), "=r"(r2), "=r"(r3) : "r"(addr));
}
__device__ __forceinline__ void ldsm4t(uint32_t addr, uint32_t& r0, uint32_t& r1,
                                       uint32_t& r2, uint32_t& r3) {
    asm volatile("ldmatrix.sync.aligned.m8n8.x4.trans.shared.b16 {%0,%1,%2,%3}, [%4];"
        : "=r"(r0), "=r"(r1), "=r"(r2), "=r"(r3) : "r"(addr));
}

__device__ __forceinline__ void mma16816(float* d, const uint32_t* a,
                                         uint32_t b0, uint32_t b1) {
    asm volatile("mma.sync.aligned.m16n8k16.row.col.f32.bf16.bf16.f32 "
        "{%0,%1,%2,%3}, {%4,%5,%6,%7}, {%8,%9}, {%0,%1,%2,%3};"
        : "+f"(d[0]), "+f"(d[1]), "+f"(d[2]), "+f"(d[3])
        : "r"(a[0]), "r"(a[1]), "r"(a[2]), "r"(a[3]), "r"(b0), "r"(b1));
}

__device__ __forceinline__ uint32_t packbf2(float a, float b) {
    __nv_bfloat162 t = __floats2bfloat162_rn(a, b);
    return *(uint32_t*)&t;
}
__device__ __forceinline__ void split2(float x0, float x1, uint32_t& hi, uint32_t& lo) {
    __nv_bfloat16 h0 = __float2bfloat16(x0);
    __nv_bfloat16 h1 = __float2bfloat16(x1);
    __nv_bfloat162 th; th.x = h0; th.y = h1;
    hi = *(uint32_t*)&th;
    __nv_bfloat162 tl;
    tl.x = __float2bfloat16(x0 - __bfloat162float(h0));
    tl.y = __float2bfloat16(x1 - __bfloat162float(h1));
    lo = *(uint32_t*)&tl;
}

// ------------------------------------------------------------------
__global__ void split_kernel(const float* __restrict__ x,
                             __nv_bfloat16* __restrict__ hi,
                             __nv_bfloat16* __restrict__ lo, int n) {
    int i = blockIdx.x * blockDim.x + threadIdx.x;
    if (i >= n) return;
    float v = x[i];
    __nv_bfloat16 h = __float2bfloat16(v);
    float r = v - __bfloat162float(h);
    hi[i] = h;
    lo[i] = __float2bfloat16(r);
}

// ------------------------------------------------------------------
__global__ void bias_kernel(const float* __restrict__ rel_bias) {
    int idx = blockIdx.x * blockDim.x + threadIdx.x;
    const int total = (2*SS-1)*HH;
    if (idx >= total) return;
    int d = idx / HH;
    int h = idx - d*HH;
    int rp = d - (SS - 1);
    int rb = (rp > 0) ? 16 : 0;
    int n = rp < 0 ? -rp : rp;
    int b;
    if (n < 8) {
        b = n;
    } else {
        double v = log((double)n / 8.0) / log(16.0) * 8.0;
        int large = 8 + (int)v;
        b = large < 15 ? large : 15;
    }
    g_bias[idx] = rel_bias[(rb + b)*HH + h];
}

// ------------------------------------------------------------------
// HMMA bf16x3 GEMM: C[m,n] = sum_k A[m,k]*W[n,k]
// mode 0: C fp32 row-major [4096,1024]
// mode 2: QKV fused (grid.x = 24): tensor t=nt>>3, writes bf16 hi/lo head-split
// ------------------------------------------------------------------
#define BKG 32
#define STAGES 3
#define TENSOR_BYTES (128*64)
#define STAGE_BYTES  (4*TENSOR_BYTES)
#define GEMM_SMEM    (STAGES*STAGE_BYTES)

__global__ void __launch_bounds__(256, 2) gemm_mma_kernel(
    const __nv_bfloat16* __restrict__ Ahi, const __nv_bfloat16* __restrict__ Alo,
    const __nv_bfloat16* __restrict__ Whi, const __nv_bfloat16* __restrict__ Wlo,
    float* __restrict__ C,
    __nv_bfloat16* __restrict__ Chi, __nv_bfloat16* __restrict__ Clo,
    int mode)
{
    extern __shared__ __align__(128) char smem[];
    const uint32_t sb = smem_u32(smem);
    const int tid  = threadIdx.x;
    const int warp = tid >> 5, lane = tid & 31;
    const int wm = warp >> 2, wn = warp & 3;
    const int nt = blockIdx.x, mt = blockIdx.y;

    const __nv_bfloat16* src0 = Ahi + (size_t)(mt*128)*1024;
    const __nv_bfloat16* src1 = Alo + (size_t)(mt*128)*1024;
    const __nv_bfloat16* src2 = Whi + (size_t)(nt*128)*1024;
    const __nv_bfloat16* src3 = Wlo + (size_t)(nt*128)*1024;
    const __nv_bfloat16* mysrc = (tid < 64) ? src0 : (tid < 128) ? src1
                               : (tid < 192) ? src2 : src3;
    const int t4 = tid >> 6;
    const int li = tid & 63;

    #define ISSUE(it) do { \
        int _stg = (it) % STAGES; \
        uint32_t _sbase = sb + _stg*STAGE_BYTES + t4*TENSOR_BYTES; \
        const __nv_bfloat16* _g = mysrc + (it)*BKG; \
        _Pragma("unroll") \
        for (int _j = 0; _j < 8; _j++) { \
            int _ch = li + _j*64; \
            int _r = _ch >> 2, _c = _ch & 3; \
            int _cs = _c ^ ((_r >> 1) & 3); \
            CP_ASYNC16(_sbase + _r*64 + _cs*16, _g + (size_t)_r*1024 + _c*8); \
        } \
    } while (0)

    ISSUE(0); CP_COMMIT();
    ISSUE(1); CP_COMMIT();

    float acc[4][4][4];
    #pragma unroll
    for (int i = 0; i < 4; i++)
        #pragma unroll
        for (int j = 0; j < 4; j++)
            #pragma unroll
            for (int q = 0; q < 4; q++) acc[i][j][q] = 0.f;

    const int arow = lane & 15;
    const int asel = lane >> 4;
    const int brow = ((lane >> 4) << 3) | (lane & 7);
    const int bsel = (lane >> 3) & 1;

    for (int it = 0; it < 32; it++) {
        CP_WAIT1();
        __syncthreads();
        if (it + 2 < 32) ISSUE(it + 2);
        CP_COMMIT();

        const uint32_t st = sb + (it % STAGES)*STAGE_BYTES;
        #pragma unroll
        for (int ks = 0; ks < 2; ks++) {
            uint32_t ah[4][4], al[4][4];
            #pragma unroll
            for (int mi = 0; mi < 4; mi++) {
                int r = wm*64 + mi*16 + arow;
                int c = 2*ks + asel;
                uint32_t off = (uint32_t)(r*64 + ((c ^ ((r>>1)&3))*16));
                ldsm4(st + off,               ah[mi][0], ah[mi][1], ah[mi][2], ah[mi][3]);
                ldsm4(st + TENSOR_BYTES + off, al[mi][0], al[mi][1], al[mi][2], al[mi][3]);
            }
            uint32_t bh2[2][4], bl2[2][4];
            #pragma unroll
            for (int np = 0; np < 2; np++) {
                int r = wn*32 + np*16 + brow;
                int c = 2*ks + bsel;
                uint32_t off = (uint32_t)(r*64 + ((c ^ ((r>>1)&3))*16));
                ldsm4(st + 2*TENSOR_BYTES + off, bh2[np][0], bh2[np][1], bh2[np][2], bh2[np][3]);
                ldsm4(st + 3*TENSOR_BYTES + off, bl2[np][0], bl2[np][1], bl2[np][2], bl2[np][3]);
            }
            #pragma unroll
            for (int mi = 0; mi < 4; mi++)
                #pragma unroll
                for (int ni = 0; ni < 4; ni++) {
                    uint32_t b0h = bh2[ni>>1][(ni&1)*2], b1h = bh2[ni>>1][(ni&1)*2+1];
                    uint32_t b0l = bl2[ni>>1][(ni&1)*2], b1l = bl2[ni>>1][(ni&1)*2+1];
                    mma16816(acc[mi][ni], ah[mi], b0h, b1h);
                    mma16816(acc[mi][ni], ah[mi], b0l, b1l);
                    mma16816(acc[mi][ni], al[mi], b0h, b1h);
                }
        }
    }
    #undef ISSUE

    const int lrow = lane >> 2;
    const int lcol = (lane & 3)*2;
    if (mode == 0) {
        const int mrow0 = mt*128 + wm*64;
        const int ncol0 = nt*128 + wn*32;
        #pragma unroll
        for (int mi = 0; mi < 4; mi++)
            #pragma unroll
            for (int ni = 0; ni < 4; ni++) {
                int m0 = mrow0 + mi*16 + lrow;
                int n0 = ncol0 + ni*8 + lcol;
                *(float2*)(C + (size_t)m0*1024 + n0) =
                    make_float2(acc[mi][ni][0], acc[mi][ni][1]);
                *(float2*)(C + (size_t)(m0+8)*1024 + n0) =
                    make_float2(acc[mi][ni][2], acc[mi][ni][3]);
            }
    } else {
        const int t = nt >> 3;
        const size_t tbase = (size_t)t * 4194304;
        const int mrow0 = mt*128 + wm*64;
        const int ncol0 = (nt & 7)*128 + wn*32;
        #pragma unroll
        for (int mi = 0; mi < 4; mi++)
            #pragma unroll
            for (int ni = 0; ni < 4; ni++) {
                int m0 = mrow0 + mi*16 + lrow;
                int m1 = m0 + 8;
                int n0 = ncol0 + ni*8 + lcol;
                int h = n0 >> 6, dk = n0 & 63;
                int b0 = m0 >> 10, s0 = m0 & 1023;
                int b1 = m1 >> 10, s1 = m1 & 1023;
                size_t i0 = tbase + ((size_t)((b0*HH + h)*SS + s0))*DKK + dk;
                size_t i1 = tbase + ((size_t)((b1*HH + h)*SS + s1))*DKK + dk;
                uint32_t hi, lo;
                split2(acc[mi][ni][0], acc[mi][ni][1], hi, lo);
                *(uint32_t*)&Chi[i0] = hi;
                *(uint32_t*)&Clo[i0] = lo;
                split2(acc[mi][ni][2], acc[mi][ni][3], hi, lo);
                *(uint32_t*)&Chi[i1] = hi;
                *(uint32_t*)&Clo[i1] = lo;
            }
    }
}

// ------------------------------------------------------------------
// Fused flash attention, bf16 tiles via cp.async, 2-stage pipeline.
// ------------------------------------------------------------------
#define T16 16384
#define FS_QH 0
#define FS_QL T16
#define FS_ST0 (2*T16)
#define FS_ST1 (6*T16)
#define FS_BIAS (10*T16)
#define FLASH_SMEM (10*T16 + 1024)

#define SWZ(r, c) ((uint32_t)((r)*128 + (((c) ^ ((r)&7))*16)))

__global__ void __launch_bounds__(256, 1) flash_kernel() {
    extern __shared__ __align__(128) char smem[];
    const uint32_t sb = smem_u32(smem);
    float* bias_s = (float*)(smem + FS_BIAS);

    const int tid  = threadIdx.x;
    const int w = tid >> 5, lane = tid & 31;
    const int mbase = blockIdx.x * 128;
    const int bh = blockIdx.y;
    const int b = bh >> 4, h = bh & 15;

    const size_t base = (size_t)bh*SS*DKK;
    const __nv_bfloat16* Qh = g_qkv_hi + base + (size_t)mbase*DKK;
    const __nv_bfloat16* Ql = g_qkv_lo + base + (size_t)mbase*DKK;
    const __nv_bfloat16* Kh = g_qkv_hi + 4194304 + base;
    const __nv_bfloat16* Kl = g_qkv_lo + 4194304 + base;
    const __nv_bfloat16* Vh = g_qkv_hi + 8388608 + base;
    const __nv_bfloat16* Vl = g_qkv_lo + 8388608 + base;

    // prologue: Q + KV stage 0 (group 0), KV stage 1 (group 1)
    #pragma unroll
    for (int i = 0; i < 4; i++) {
        int id = tid + i*256;
        int r = id >> 3, c = id & 7;
        uint32_t off = SWZ(r, c);
        const size_t go = (size_t)r*64 + c*8;
        CP_ASYNC16(sb + FS_QH + off, Qh + go);
        CP_ASYNC16(sb + FS_QL + off, Ql + go);
    }
    #define ISSUE_KV(j, stoff) do { \
        const size_t _jo = (size_t)(j)*128*64; \
        _Pragma("unroll") \
        for (int _i = 0; _i < 4; _i++) { \
            int _id = tid + _i*256; \
            int _r = _id >> 3, _c = _id & 7; \
            uint32_t _off = SWZ(_r, _c); \
            const size_t _go = _jo + (size_t)_r*64 + _c*8; \
            CP_ASYNC16(sb + (stoff) + 0*T16 + _off, Kh + _go); \
            CP_ASYNC16(sb + (stoff) + 1*T16 + _off, Kl + _go); \
            CP_ASYNC16(sb + (stoff) + 2*T16 + _off, Vh + _go); \
            CP_ASYNC16(sb + (stoff) + 3*T16 + _off, Vl + _go); \
        } \
    } while (0)
    ISSUE_KV(0, FS_ST0); CP_COMMIT();
    ISSUE_KV(1, FS_ST1); CP_COMMIT();

    float Oacc[8][4];
    #pragma unroll
    for (int d = 0; d < 8; d++)
        #pragma unroll
        for (int q = 0; q < 4; q++) Oacc[d][q] = 0.f;
    float mrun0 = -1e30f, mrun1 = -1e30f, lrun0 = 0.f, lrun1 = 0.f;

    const int r0 = lane >> 2;
    const int colb = (lane & 3)*2;
    const int rl0 = w*16 + r0;
    const int rl1 = rl0 + 8;

    const int a_r = w*16 + (lane & 15);
    const int a_s = lane >> 4;
    const int b_r = ((lane >> 4) << 3) | (lane & 7);
    const int b_s = (lane >> 3) & 1;
    const int v_k = ((lane >> 3) & 1)*8 + (lane & 7);
    const int v_c = lane >> 4;

    for (int j = 0; j < 8; j++) {
        if (j < 7) { CP_WAIT1(); } else { CP_WAIT0(); }
        __syncthreads();
        if (tid < 255) {
            int delta = j*128 - mbase + (tid - 127);
            bias_s[tid] = g_bias[(size_t)(delta + SS - 1)*HH + h];
        }
        __syncthreads();

        const uint32_t st = sb + ((j & 1) ? FS_ST1 : FS_ST0);

        // ---- S = Q K^T (bf16x3) ----
        float sacc[16][4];
        #pragma unroll
        for (int nt = 0; nt < 16; nt++)
            #pragma unroll
            for (int q = 0; q < 4; q++) sacc[nt][q] = 0.f;

        #pragma unroll
        for (int ks = 0; ks < 4; ks++) {
            uint32_t aqh[4], aql[4];
            uint32_t aoff = SWZ(a_r, 2*ks + a_s);
            ldsm4(sb + FS_QH + aoff, aqh[0], aqh[1], aqh[2], aqh[3]);
            ldsm4(sb + FS_QL + aoff, aql[0], aql[1], aql[2], aql[3]);
            #pragma unroll
            for (int np = 0; np < 8; np++) {
                uint32_t kh[4], kl[4];
                uint32_t boff = SWZ(np*16 + b_r, 2*ks + b_s);
                ldsm4(st + 0*T16 + boff, kh[0], kh[1], kh[2], kh[3]);
                ldsm4(st + 1*T16 + boff, kl[0], kl[1], kl[2], kl[3]);
                mma16816(sacc[2*np],   aqh, kh[0], kh[1]);
                mma16816(sacc[2*np],   aqh, kl[0], kl[1]);
                mma16816(sacc[2*np],   aql, kh[0], kh[1]);
                mma16816(sacc[2*np+1], aqh, kh[2], kh[3]);
                mma16816(sacc[2*np+1], aqh, kl[2], kl[3]);
                mma16816(sacc[2*np+1], aql, kh[2], kh[3]);
            }
        }

        // ---- bias ----
        #pragma unroll
        for (int nt = 0; nt < 16; nt++) {
            int col = nt*8 + colb;
            sacc[nt][0] += bias_s[col     - rl0 + 127];
            sacc[nt][1] += bias_s[col + 1 - rl0 + 127];
            sacc[nt][2] += bias_s[col     - rl1 + 127];
            sacc[nt][3] += bias_s[col + 1 - rl1 + 127];
        }

        // ---- online softmax ----
        float mx0 = -1e30f, mx1 = -1e30f;
        #pragma unroll
        for (int nt = 0; nt < 16; nt++) {
            mx0 = fmaxf(mx0, fmaxf(sacc[nt][0], sacc[nt][1]));
            mx1 = fmaxf(mx1, fmaxf(sacc[nt][2], sacc[nt][3]));
        }
        mx0 = fmaxf(mx0, __shfl_xor_sync(0xffffffffu, mx0, 1));
        mx0 = fmaxf(mx0, __shfl_xor_sync(0xffffffffu, mx0, 2));
        mx1 = fmaxf(mx1, __shfl_xor_sync(0xffffffffu, mx1, 1));
        mx1 = fmaxf(mx1, __shfl_xor_sync(0xffffffffu, mx1, 2));

        float mn0 = fmaxf(mrun0, mx0);
        float mn1 = fmaxf(mrun1, mx1);
        float al0 = __expf(mrun0 - mn0);
        float al1 = __expf(mrun1 - mn1);
        mrun0 = mn0; mrun1 = mn1;

        float rs0 = 0.f, rs1 = 0.f;
        #pragma unroll
        for (int nt = 0; nt < 16; nt++) {
            sacc[nt][0] = __expf(sacc[nt][0] - mn0);
            sacc[nt][1] = __expf(sacc[nt][1] - mn0);
            sacc[nt][2] = __expf(sacc[nt][2] - mn1);
            sacc[nt][3] = __expf(sacc[nt][3] - mn1);
            rs0 += sacc[nt][0] + sacc[nt][1];
            rs1 += sacc[nt][2] + sacc[nt][3];
        }
        rs0 += __shfl_xor_sync(0xffffffffu, rs0, 1);
        rs0 += __shfl_xor_sync(0xffffffffu, rs0, 2);
        rs1 += __shfl_xor_sync(0xffffffffu, rs1, 1);
        rs1 += __shfl_xor_sync(0xffffffffu, rs1, 2);
        lrun0 = lrun0*al0 + rs0;
        lrun1 = lrun1*al1 + rs1;

        #pragma unroll
        for (int d = 0; d < 8; d++) {
            Oacc[d][0] *= al0; Oacc[d][1] *= al0;
            Oacc[d][2] *= al1; Oacc[d][3] *= al1;
        }

        // ---- O += P V (bf16x3) ----
        #pragma unroll
        for (int ks = 0; ks < 8; ks++) {
            uint32_t ph[4], pl[4];
            {
                split2(sacc[2*ks][0],   sacc[2*ks][1],   ph[0], pl[0]);
                split2(sacc[2*ks][2],   sacc[2*ks][3],   ph[1], pl[1]);
                split2(sacc[2*ks+1][0], sacc[2*ks+1][1], ph[2], pl[2]);
                split2(sacc[2*ks+1][2], sacc[2*ks+1][3], ph[3], pl[3]);
            }
            #pragma unroll
            for (int dp = 0; dp < 4; dp++) {
                uint32_t vh[4], vl[4];
                uint32_t voff = SWZ(ks*16 + v_k, dp*2 + v_c);
                ldsm4t(st + 2*T16 + voff, vh[0], vh[1], vh[2], vh[3]);
                ldsm4t(st + 3*T16 + voff, vl[0], vl[1], vl[2], vl[3]);
                mma16816(Oacc[2*dp],   ph, vh[0], vh[1]);
                mma16816(Oacc[2*dp],   ph, vl[0], vl[1]);
                mma16816(Oacc[2*dp],   pl, vh[0], vh[1]);
                mma16816(Oacc[2*dp+1], ph, vh[2], vh[3]);
                mma16816(Oacc[2*dp+1], ph, vl[2], vl[3]);
                mma16816(Oacc[2*dp+1], pl, vh[2], vh[3]);
            }
        }

        __syncthreads();   // all warps done reading stage j&1
        if (j + 2 < 8) {
            ISSUE_KV(j + 2, ((j & 1) ? FS_ST1 : FS_ST0));
            CP_COMMIT();
        }
    }
    #undef ISSUE_KV

    // ---- epilogue: normalize + write ctx as bf16 hi/lo ----
    float inv0 = 1.0f / lrun0;
    float inv1 = 1.0f / lrun1;
    int m0 = mbase + rl0;
    int m1 = mbase + rl1;
    #pragma unroll
    for (int dt = 0; dt < 8; dt++) {
        int d = dt*8 + colb;
        size_t i0 = ((size_t)(b*SS + m0))*DD + h*DKK + d;
        size_t i1 = ((size_t)(b*SS + m1))*DD + h*DKK + d;
        uint32_t hi, lo;
        split2(Oacc[dt][0]*inv0, Oacc[dt][1]*inv0, hi, lo);
        *(uint32_t*)&g_ctx_hi[i0] = hi;
        *(uint32_t*)&g_ctx_lo[i0] = lo;
        split2(Oacc[dt][2]*inv1, Oacc[dt][3]*inv1, hi, lo);
        *(uint32_t*)&g_ctx_hi[i1] = hi;
        *(uint32_t*)&g_ctx_lo[i1] = lo;
    }
}

// ------------------------------------------------------------------
extern "C" void kernel_launch(void* const* d_in, const int* in_sizes, int n_in,
                              void* d_out, int out_size) {
    const float* hidden   = (const float*)d_in[0];
    const float* Wq       = (const float*)d_in[1];
    const float* Wk       = (const float*)d_in[2];
    const float* Wv       = (const float*)d_in[3];
    const float* Wo       = (const float*)d_in[4];
    const float* rel_bias = (const float*)d_in[5];
    float* out = (float*)d_out;

    __nv_bfloat16 *pahi, *palo, *pwhi, *pwlo, *pqkvh, *pqkvl, *pchi, *pclo;
    cudaGetSymbolAddress((void**)&pahi, g_ahi);
    cudaGetSymbolAddress((void**)&palo, g_alo);
    cudaGetSymbolAddress((void**)&pwhi, g_whi);
    cudaGetSymbolAddress((void**)&pwlo, g_wlo);
    cudaGetSymbolAddress((void**)&pqkvh, g_qkv_hi);
    cudaGetSymbolAddress((void**)&pqkvl, g_qkv_lo);
    cudaGetSymbolAddress((void**)&pchi, g_ctx_hi);
    cudaGetSymbolAddress((void**)&pclo, g_ctx_lo);

    cudaFuncSetAttribute(gemm_mma_kernel,
                         cudaFuncAttributeMaxDynamicSharedMemorySize, GEMM_SMEM);
    cudaFuncSetAttribute(flash_kernel,
                         cudaFuncAttributeMaxDynamicSharedMemorySize, FLASH_SMEM);

    const int nA = 4096*1024;
    const int nW = 1024*1024;

    bias_kernel<<<((2*SS-1)*HH + 255)/256, 256>>>(rel_bias);
    split_kernel<<<(nA + 255)/256, 256>>>(hidden, pahi, palo, nA);
    split_kernel<<<(nW + 255)/256, 256>>>(Wq, pwhi,          pwlo,          nW);
    split_kernel<<<(nW + 255)/256, 256>>>(Wk, pwhi + 1048576, pwlo + 1048576, nW);
    split_kernel<<<(nW + 255)/256, 256>>>(Wv, pwhi + 2097152, pwlo + 2097152, nW);
    split_kernel<<<(nW + 255)/256, 256>>>(Wo, pwhi + 3145728, pwlo + 3145728, nW);

    // fused QKV projection -> bf16 hi/lo head-split
    gemm_mma_kernel<<<dim3(24, 32), 256, GEMM_SMEM>>>(
        pahi, palo, pwhi, pwlo, nullptr, pqkvh, pqkvl, 2);

    // fused attention
    flash_kernel<<<dim3(8, BH), 256, FLASH_SMEM>>>();

    // output projection (fp32 out)
    gemm_mma_kernel<<<dim3(8, 32), 256, GEMM_SMEM>>>(
        pchi, pclo, pwhi + 3145728, pwlo + 3145728, out, nullptr, nullptr, 0);
}